// round 1
// baseline (speedup 1.0000x reference)
#include <cuda_runtime.h>
#include <math.h>

#define HID    1024
#define NHEADS 16
#define HDIM   64
#define SEQ    2048
#define BATCH  2
#define TOKS   (BATCH*SEQ)   // 4096

// Scratch for Q,K,V in [B, NH, S, HD] layout (16 MB each)
__device__ float g_Q[BATCH*NHEADS*SEQ*HDIM];
__device__ float g_K[BATCH*NHEADS*SEQ*HDIM];
__device__ float g_V[BATCH*NHEADS*SEQ*HDIM];

// ---------------------------------------------------------------------------
// Kernel 1: QKV projection.  C[t,o] = sum_h hidden[t,h]*W[o,h] + b[o]
// Both operands K-major (NT GEMM). 128x128 block tile, BK=16, 8x8 per thread.
// blockIdx.z selects {Q,K,V}. Output scattered to [B,NH,S,HD] scratch.
// ---------------------------------------------------------------------------
__global__ __launch_bounds__(256, 2)
void qkv_kernel(const float* __restrict__ hidden,
                const float* __restrict__ Wq, const float* __restrict__ bq,
                const float* __restrict__ Wk, const float* __restrict__ bk,
                const float* __restrict__ Wv, const float* __restrict__ bv)
{
    // pitch 20 -> float4 writes hit all 32 banks; reads are 2-addr broadcast (A)
    // and stride-20 (B, 2-way worst case).
    __shared__ float As[128][20];
    __shared__ float Bs[128][20];

    const int z = blockIdx.z;
    const float* W    = (z == 0) ? Wq : ((z == 1) ? Wk : Wv);
    const float* bias = (z == 0) ? bq : ((z == 1) ? bk : bv);
    float* dst        = (z == 0) ? g_Q : ((z == 1) ? g_K : g_V);

    const int tid = threadIdx.x;
    const int tm  = tid >> 4;   // 0..15
    const int tn  = tid & 15;   // 0..15
    const int m0  = blockIdx.y * 128;
    const int n0  = blockIdx.x * 128;

    float acc[8][8];
    #pragma unroll
    for (int i = 0; i < 8; i++)
        #pragma unroll
        for (int j = 0; j < 8; j++) acc[i][j] = 0.0f;

    for (int kt = 0; kt < HID; kt += 16) {
        #pragma unroll
        for (int r = 0; r < 2; r++) {
            int idx = tid + r * 256;          // 0..511 float4 slots
            int row = idx >> 2;               // 0..127
            int k4  = (idx & 3) * 4;          // 0,4,8,12
            float4 a = *(const float4*)&hidden[(size_t)(m0 + row) * HID + kt + k4];
            float4 b = *(const float4*)&W[(size_t)(n0 + row) * HID + kt + k4];
            *(float4*)&As[row][k4] = a;
            *(float4*)&Bs[row][k4] = b;
        }
        __syncthreads();

        #pragma unroll
        for (int k = 0; k < 16; k++) {
            float rm[8], rn[8];
            #pragma unroll
            for (int i = 0; i < 8; i++) rm[i] = As[tm + i * 16][k];
            #pragma unroll
            for (int j = 0; j < 8; j++) rn[j] = Bs[tn + j * 16][k];
            #pragma unroll
            for (int i = 0; i < 8; i++)
                #pragma unroll
                for (int j = 0; j < 8; j++)
                    acc[i][j] = fmaf(rm[i], rn[j], acc[i][j]);
        }
        __syncthreads();
    }

    #pragma unroll
    for (int i = 0; i < 8; i++) {
        int t = m0 + tm + i * 16;
        int b = t >> 11;            // /2048
        int s = t & (SEQ - 1);
        #pragma unroll
        for (int j = 0; j < 8; j++) {
            int o = n0 + tn + j * 16;
            int h = o >> 6;
            int d = o & (HDIM - 1);
            dst[(((size_t)b * NHEADS + h) * SEQ + s) * HDIM + d] = acc[i][j] + bias[o];
        }
    }
}

// ---------------------------------------------------------------------------
// Kernel 2: flash attention, fp32.  One block = 64 q-rows of one (b,h);
// loops over 2048 keys in 64-key tiles. Online softmax. K and V share one
// SMEM buffer; exp'd scores staged in SMEM P tile for the PV product.
// Thread (ty,tx) in 16x16 grid owns q-rows {ty+16i} and kv/d-cols {tx+16j}
// (stride-16 register tiling => conflict-free LDS).
// ---------------------------------------------------------------------------
#define KV_PITCH 68   // 2-way worst case on stride-68 K reads

__global__ __launch_bounds__(256, 2)
void attn_kernel(float* __restrict__ out)
{
    extern __shared__ float sm[];
    float* Qs  = sm;                    // 64*64
    float* KVs = sm + 64 * 64;          // 64*KV_PITCH
    float* Ps  = KVs + 64 * KV_PITCH;   // 64*64

    const int tid = threadIdx.x;
    const int ty  = tid >> 4;           // 0..15
    const int tx  = tid & 15;           // 0..15
    const int q0  = blockIdx.x * 64;
    const int bh  = blockIdx.y;         // 0..31
    const size_t base = (size_t)bh * SEQ * HDIM;

    // load Q tile, pre-scaled by 1/sqrt(HD)=0.125
    #pragma unroll
    for (int r = 0; r < 4; r++) {
        int idx = tid + r * 256;
        int row = idx >> 4;
        int d4  = (idx & 15) * 4;
        float4 v = *(const float4*)&g_Q[base + (size_t)(q0 + row) * HDIM + d4];
        v.x *= 0.125f; v.y *= 0.125f; v.z *= 0.125f; v.w *= 0.125f;
        *(float4*)&Qs[row * 64 + d4] = v;
    }

    float m[4], l[4], o[4][4];
    #pragma unroll
    for (int i = 0; i < 4; i++) {
        m[i] = -INFINITY; l[i] = 0.0f;
        #pragma unroll
        for (int j = 0; j < 4; j++) o[i][j] = 0.0f;
    }

    for (int kt = 0; kt < SEQ; kt += 64) {
        __syncthreads();   // prev iter done reading KVs(V) and Ps
        #pragma unroll
        for (int r = 0; r < 4; r++) {
            int idx = tid + r * 256;
            int row = idx >> 4;
            int d4  = (idx & 15) * 4;
            float4 v = *(const float4*)&g_K[base + (size_t)(kt + row) * HDIM + d4];
            *(float4*)&KVs[row * KV_PITCH + d4] = v;
        }
        __syncthreads();

        // scores s[i][j] = q_i . k_j (already /8 via Qs scaling)
        float s[4][4];
        #pragma unroll
        for (int i = 0; i < 4; i++)
            #pragma unroll
            for (int j = 0; j < 4; j++) s[i][j] = 0.0f;

        #pragma unroll 8
        for (int d = 0; d < 64; d++) {
            float rq[4], rk[4];
            #pragma unroll
            for (int i = 0; i < 4; i++) rq[i] = Qs[(ty + i * 16) * 64 + d];
            #pragma unroll
            for (int j = 0; j < 4; j++) rk[j] = KVs[(tx + j * 16) * KV_PITCH + d];
            #pragma unroll
            for (int i = 0; i < 4; i++)
                #pragma unroll
                for (int j = 0; j < 4; j++)
                    s[i][j] = fmaf(rq[i], rk[j], s[i][j]);
        }

        // online softmax per q-row (row spread across the 16 tx lanes)
        #pragma unroll
        for (int i = 0; i < 4; i++) {
            float mt = fmaxf(fmaxf(s[i][0], s[i][1]), fmaxf(s[i][2], s[i][3]));
            #pragma unroll
            for (int off = 8; off >= 1; off >>= 1)
                mt = fmaxf(mt, __shfl_xor_sync(0xffffffffu, mt, off, 16));
            float mn    = fmaxf(m[i], mt);
            float scale = __expf(m[i] - mn);
            m[i] = mn;
            float ps = 0.0f;
            #pragma unroll
            for (int j = 0; j < 4; j++) {
                float p = __expf(s[i][j] - mn);
                ps += p;
                Ps[(ty + i * 16) * 64 + tx + j * 16] = p;
            }
            #pragma unroll
            for (int off = 8; off >= 1; off >>= 1)
                ps += __shfl_xor_sync(0xffffffffu, ps, off, 16);
            l[i] = l[i] * scale + ps;
            #pragma unroll
            for (int j = 0; j < 4; j++) o[i][j] *= scale;
        }
        __syncthreads();   // Ps visible; everyone done reading KVs(K)

        #pragma unroll
        for (int r = 0; r < 4; r++) {
            int idx = tid + r * 256;
            int row = idx >> 4;
            int d4  = (idx & 15) * 4;
            float4 v = *(const float4*)&g_V[base + (size_t)(kt + row) * HDIM + d4];
            *(float4*)&KVs[row * KV_PITCH + d4] = v;
        }
        __syncthreads();

        // o[i][jd] += sum_j P[row_i][j] * V[j][dcol_jd]
        #pragma unroll 8
        for (int j = 0; j < 64; j++) {
            float rp[4], rv[4];
            #pragma unroll
            for (int i = 0; i < 4; i++) rp[i] = Ps[(ty + i * 16) * 64 + j];
            #pragma unroll
            for (int jd = 0; jd < 4; jd++) rv[jd] = KVs[j * KV_PITCH + tx + jd * 16];
            #pragma unroll
            for (int i = 0; i < 4; i++)
                #pragma unroll
                for (int jd = 0; jd < 4; jd++)
                    o[i][jd] = fmaf(rp[i], rv[jd], o[i][jd]);
        }
    }

    const int b = bh >> 4;
    const int h = bh & (NHEADS - 1);
    #pragma unroll
    for (int i = 0; i < 4; i++) {
        float inv = 1.0f / l[i];
        int srow  = q0 + ty + i * 16;
        #pragma unroll
        for (int jd = 0; jd < 4; jd++) {
            int d = tx + jd * 16;
            out[((size_t)b * SEQ + srow) * HID + h * HDIM + d] = o[i][jd] * inv;
        }
    }
}

// ---------------------------------------------------------------------------
extern "C" void kernel_launch(void* const* d_in, const int* in_sizes, int n_in,
                              void* d_out, int out_size)
{
    const float* hidden = (const float*)d_in[0];
    const float* Wq = (const float*)d_in[1];
    const float* bq = (const float*)d_in[2];
    const float* Wk = (const float*)d_in[3];
    const float* bk = (const float*)d_in[4];
    const float* Wv = (const float*)d_in[5];
    const float* bv = (const float*)d_in[6];
    float* out = (float*)d_out;

    qkv_kernel<<<dim3(HID / 128, TOKS / 128, 3), 256>>>(hidden, Wq, bq, Wk, bk, Wv, bv);

    const int smem = (64 * 64 + 64 * KV_PITCH + 64 * 64) * (int)sizeof(float); // 50176 B
    cudaFuncSetAttribute(attn_kernel, cudaFuncAttributeMaxDynamicSharedMemorySize, smem);
    attn_kernel<<<dim3(SEQ / 64, BATCH * NHEADS), 256, smem>>>(out);
}

// round 2
// speedup vs baseline: 1.0930x; 1.0930x over previous
#include <cuda_runtime.h>
#include <math.h>

#define HID    1024
#define NHEADS 16
#define HDIM   64
#define SEQ    2048
#define BATCH  2
#define TOKS   (BATCH*SEQ)   // 4096

typedef unsigned long long ull;

__device__ __forceinline__ ull f2_fma(ull a, ull b, ull c) {
    ull d;
    asm("fma.rn.f32x2 %0, %1, %2, %3;" : "=l"(d) : "l"(a), "l"(b), "l"(c));
    return d;
}
__device__ __forceinline__ ull f2_mul(ull a, ull b) {
    ull d;
    asm("mul.rn.f32x2 %0, %1, %2;" : "=l"(d) : "l"(a), "l"(b));
    return d;
}
__device__ __forceinline__ ull f2_pack(float lo, float hi) {
    ull d;
    asm("mov.b64 %0, {%1, %2};" : "=l"(d) : "f"(lo), "f"(hi));
    return d;
}
__device__ __forceinline__ ull f2_dup(float x) { return f2_pack(x, x); }
__device__ __forceinline__ void f2_unpack(float& lo, float& hi, ull v) {
    asm("mov.b64 {%0, %1}, %2;" : "=f"(lo), "=f"(hi) : "l"(v));
}

// Scratch for Q,K,V in [B, NH, S, HD] layout
__device__ float g_Q[BATCH*NHEADS*SEQ*HDIM];
__device__ float g_K[BATCH*NHEADS*SEQ*HDIM];
__device__ float g_V[BATCH*NHEADS*SEQ*HDIM];

// ---------------------------------------------------------------------------
// Kernel 1: QKV projection with f32x2.  C[t,o] = sum_h hidden[t,h]*W[o,h]+b[o]
// 128x128 tile, BK=16, per thread 8 rows x 4 n-pairs (8 cols), acc in f32x2
// packed along N. W tile stored transposed [k][n] so n-pairs load as LDS.64.
// ---------------------------------------------------------------------------
#define BP 130   // Bst pitch (floats): transpose STS conflict-free, LDS.64 cf

__global__ __launch_bounds__(256, 2)
void qkv_kernel(const float* __restrict__ hidden,
                const float* __restrict__ Wq, const float* __restrict__ bq,
                const float* __restrict__ Wk, const float* __restrict__ bk,
                const float* __restrict__ Wv, const float* __restrict__ bv)
{
    __shared__ float As[128][20];
    __shared__ float Bst[16*BP];

    const int z = blockIdx.z;
    const float* W    = (z == 0) ? Wq : ((z == 1) ? Wk : Wv);
    const float* bias = (z == 0) ? bq : ((z == 1) ? bk : bv);
    float* dst        = (z == 0) ? g_Q : ((z == 1) ? g_K : g_V);

    const int tid = threadIdx.x;
    const int tm  = tid >> 4;   // 0..15 (row groups)
    const int tn  = tid & 15;   // 0..15 (n-pair groups)
    const int m0  = blockIdx.y * 128;
    const int n0  = blockIdx.x * 128;

    ull acc2[8][4];
    #pragma unroll
    for (int i = 0; i < 8; i++)
        #pragma unroll
        for (int j = 0; j < 4; j++) acc2[i][j] = 0ull;

    for (int kt = 0; kt < HID; kt += 16) {
        #pragma unroll
        for (int r = 0; r < 2; r++) {
            int idx = tid + r * 256;          // 0..511
            int row = idx >> 2;               // 0..127
            int k4  = (idx & 3) * 4;          // 0,4,8,12
            float4 a = *(const float4*)&hidden[(size_t)(m0 + row) * HID + kt + k4];
            *(float4*)&As[row][k4] = a;
            float4 w = *(const float4*)&W[(size_t)(n0 + row) * HID + kt + k4];
            Bst[(k4 + 0) * BP + row] = w.x;
            Bst[(k4 + 1) * BP + row] = w.y;
            Bst[(k4 + 2) * BP + row] = w.z;
            Bst[(k4 + 3) * BP + row] = w.w;
        }
        __syncthreads();

        #pragma unroll
        for (int k = 0; k < 16; k++) {
            ull rm2[8], rn2[4];
            #pragma unroll
            for (int i = 0; i < 8; i++) rm2[i] = f2_dup(As[tm + i * 16][k]);
            #pragma unroll
            for (int j = 0; j < 4; j++)
                rn2[j] = *(const ull*)&Bst[k * BP + 2 * tn + 32 * j];
            #pragma unroll
            for (int i = 0; i < 8; i++)
                #pragma unroll
                for (int j = 0; j < 4; j++)
                    acc2[i][j] = f2_fma(rm2[i], rn2[j], acc2[i][j]);
        }
        __syncthreads();
    }

    #pragma unroll
    for (int i = 0; i < 8; i++) {
        int t = m0 + tm + i * 16;
        int b = t >> 11;
        int s = t & (SEQ - 1);
        #pragma unroll
        for (int j = 0; j < 4; j++) {
            int o = n0 + 2 * tn + 32 * j;     // even, o+1 same head
            float c0, c1;
            f2_unpack(c0, c1, acc2[i][j]);
            int h = o >> 6;
            int d = o & (HDIM - 1);
            float2 v = make_float2(c0 + bias[o], c1 + bias[o + 1]);
            *(float2*)&dst[(((size_t)b * NHEADS + h) * SEQ + s) * HDIM + d] = v;
        }
    }
}

// ---------------------------------------------------------------------------
// Kernel 2: flash attention with f32x2.
// Block: 128 q-rows x all keys in 64-key tiles. 512 threads.
// ty=tid>>4 (0..31): rows 4*ty..4*ty+3.  tx=tid&15: keys tx+16j, j=0..3.
// QK: f32x2 packed along d (even/odd partials; summed before softmax).
// PV: f32x2 packed along row pairs; P staged key-major in SMEM.
// ---------------------------------------------------------------------------
#define QROWS 128
#define KTILE 64
#define QP 68     // Qs/Ks/Vs pitch
#define PP 132    // Ps pitch (rows dim)

__global__ __launch_bounds__(512, 1)
void attn_kernel(float* __restrict__ out)
{
    extern __shared__ float sm[];
    float* Qs = sm;                           // [128][68]
    float* Ks = Qs + QROWS * QP;              // [64][68]
    float* Vs = Ks + KTILE * QP;              // [64][68]
    float* Ps = Vs + KTILE * QP;              // [64][132]  key-major

    const int tid = threadIdx.x;
    const int ty  = tid >> 4;                 // 0..31
    const int tx  = tid & 15;                 // 0..15
    const int q0  = blockIdx.x * QROWS;
    const int bh  = blockIdx.y;               // 0..31
    const size_t base = (size_t)bh * SEQ * HDIM;
    const int r0 = 4 * ty;                    // first of 4 owned rows

    // load Q tile (pre-scaled by 1/sqrt(HD) = 0.125)
    #pragma unroll
    for (int r = 0; r < 4; r++) {
        int idx = tid + r * 512;
        int row = idx >> 4;
        int d4  = (idx & 15) * 4;
        float4 v = *(const float4*)&g_Q[base + (size_t)(q0 + row) * HDIM + d4];
        v.x *= 0.125f; v.y *= 0.125f; v.z *= 0.125f; v.w *= 0.125f;
        *(float4*)&Qs[row * QP + d4] = v;
    }

    float m[4], l[4];
    ull o2[2][4];
    #pragma unroll
    for (int i = 0; i < 4; i++) { m[i] = -INFINITY; l[i] = 0.0f; }
    #pragma unroll
    for (int i2 = 0; i2 < 2; i2++)
        #pragma unroll
        for (int jd = 0; jd < 4; jd++) o2[i2][jd] = 0ull;

    for (int kt = 0; kt < SEQ; kt += KTILE) {
        __syncthreads();   // previous PV done with Vs/Ps
        #pragma unroll
        for (int r = 0; r < 2; r++) {
            int idx = tid + r * 512;
            int row = idx >> 4;
            int d4  = (idx & 15) * 4;
            *(float4*)&Ks[row * QP + d4] =
                *(const float4*)&g_K[base + (size_t)(kt + row) * HDIM + d4];
            *(float4*)&Vs[row * QP + d4] =
                *(const float4*)&g_V[base + (size_t)(kt + row) * HDIM + d4];
        }
        __syncthreads();

        // ---- QK^T, d-packed f32x2 ----
        ull s2[4][4];
        #pragma unroll
        for (int i = 0; i < 4; i++)
            #pragma unroll
            for (int j = 0; j < 4; j++) s2[i][j] = 0ull;

        #pragma unroll 4
        for (int d = 0; d < HDIM; d += 4) {
            ulonglong2 q2[4], k2[4];
            #pragma unroll
            for (int i = 0; i < 4; i++)
                q2[i] = *(const ulonglong2*)&Qs[(r0 + i) * QP + d];
            #pragma unroll
            for (int j = 0; j < 4; j++)
                k2[j] = *(const ulonglong2*)&Ks[(tx + 16 * j) * QP + d];
            #pragma unroll
            for (int i = 0; i < 4; i++)
                #pragma unroll
                for (int j = 0; j < 4; j++) {
                    s2[i][j] = f2_fma(q2[i].x, k2[j].x, s2[i][j]);
                    s2[i][j] = f2_fma(q2[i].y, k2[j].y, s2[i][j]);
                }
        }

        // reduce lanes -> scalar scores
        float s[4][4];
        #pragma unroll
        for (int i = 0; i < 4; i++)
            #pragma unroll
            for (int j = 0; j < 4; j++) {
                float lo, hi;
                f2_unpack(lo, hi, s2[i][j]);
                s[i][j] = lo + hi;
            }

        // ---- online softmax (rows owned per-thread, reduce across 16 tx) ----
        float sc[4];
        #pragma unroll
        for (int i = 0; i < 4; i++) {
            float mt = fmaxf(fmaxf(s[i][0], s[i][1]), fmaxf(s[i][2], s[i][3]));
            #pragma unroll
            for (int off = 8; off >= 1; off >>= 1)
                mt = fmaxf(mt, __shfl_xor_sync(0xffffffffu, mt, off, 16));
            float mn = fmaxf(m[i], mt);
            sc[i] = __expf(m[i] - mn);
            m[i] = mn;
            float ps = 0.0f;
            #pragma unroll
            for (int j = 0; j < 4; j++) {
                float p = __expf(s[i][j] - mn);
                s[i][j] = p;
                ps += p;
            }
            #pragma unroll
            for (int off = 8; off >= 1; off >>= 1)
                ps += __shfl_xor_sync(0xffffffffu, ps, off, 16);
            l[i] = l[i] * sc[i] + ps;
        }
        // rescale O accumulators (packed row pairs)
        ull sc2a = f2_pack(sc[0], sc[1]);
        ull sc2b = f2_pack(sc[2], sc[3]);
        #pragma unroll
        for (int jd = 0; jd < 4; jd++) {
            o2[0][jd] = f2_mul(o2[0][jd], sc2a);
            o2[1][jd] = f2_mul(o2[1][jd], sc2b);
        }
        // stage P key-major: Ps[key][row], rows contiguous -> STS.128
        #pragma unroll
        for (int j = 0; j < 4; j++) {
            float4 p4 = make_float4(s[0][j], s[1][j], s[2][j], s[3][j]);
            *(float4*)&Ps[(tx + 16 * j) * PP + r0] = p4;
        }
        __syncthreads();

        // ---- P @ V, row-pair-packed f32x2 ----
        #pragma unroll 2
        for (int j = 0; j < KTILE; j++) {
            ull rp0 = *(const ull*)&Ps[j * PP + r0];
            ull rp1 = *(const ull*)&Ps[j * PP + r0 + 2];
            float4 v = *(const float4*)&Vs[j * QP + 4 * tx];
            ull rv0 = f2_dup(v.x), rv1 = f2_dup(v.y);
            ull rv2 = f2_dup(v.z), rv3 = f2_dup(v.w);
            o2[0][0] = f2_fma(rp0, rv0, o2[0][0]);
            o2[0][1] = f2_fma(rp0, rv1, o2[0][1]);
            o2[0][2] = f2_fma(rp0, rv2, o2[0][2]);
            o2[0][3] = f2_fma(rp0, rv3, o2[0][3]);
            o2[1][0] = f2_fma(rp1, rv0, o2[1][0]);
            o2[1][1] = f2_fma(rp1, rv1, o2[1][1]);
            o2[1][2] = f2_fma(rp1, rv2, o2[1][2]);
            o2[1][3] = f2_fma(rp1, rv3, o2[1][3]);
        }
    }

    // epilogue
    const int b = bh >> 4;
    const int h = bh & (NHEADS - 1);
    float o[4][4];
    #pragma unroll
    for (int i2 = 0; i2 < 2; i2++)
        #pragma unroll
        for (int jd = 0; jd < 4; jd++)
            f2_unpack(o[2 * i2][jd], o[2 * i2 + 1][jd], o2[i2][jd]);

    #pragma unroll
    for (int i = 0; i < 4; i++) {
        float inv = 1.0f / l[i];
        int srow = q0 + r0 + i;
        float4 v = make_float4(o[i][0] * inv, o[i][1] * inv,
                               o[i][2] * inv, o[i][3] * inv);
        *(float4*)&out[((size_t)b * SEQ + srow) * HID + h * HDIM + 4 * tx] = v;
    }
}

// ---------------------------------------------------------------------------
extern "C" void kernel_launch(void* const* d_in, const int* in_sizes, int n_in,
                              void* d_out, int out_size)
{
    const float* hidden = (const float*)d_in[0];
    const float* Wq = (const float*)d_in[1];
    const float* bq = (const float*)d_in[2];
    const float* Wk = (const float*)d_in[3];
    const float* bk = (const float*)d_in[4];
    const float* Wv = (const float*)d_in[5];
    const float* bv = (const float*)d_in[6];
    float* out = (float*)d_out;

    qkv_kernel<<<dim3(HID / 128, TOKS / 128, 3), 256>>>(hidden, Wq, bq, Wk, bk, Wv, bv);

    const int smem = (QROWS * QP + KTILE * QP * 2 + KTILE * PP) * (int)sizeof(float); // 103424
    cudaFuncSetAttribute(attn_kernel, cudaFuncAttributeMaxDynamicSharedMemorySize, smem);
    attn_kernel<<<dim3(SEQ / QROWS, BATCH * NHEADS), 512, smem>>>(out);
}

// round 4
// speedup vs baseline: 2.8731x; 2.6287x over previous
#include <cuda_runtime.h>
#include <cuda_bf16.h>
#include <math.h>
#include <stdint.h>

#define HID    1024
#define NHEADS 16
#define HDIM   64
#define SEQ    2048
#define BATCH  2
#define TOKS   (BATCH*SEQ)   // 4096

// Scratch for Q,K,V in [B, NH, S, HD] layout (fp32)
__device__ float g_Q[BATCH*NHEADS*SEQ*HDIM];
__device__ float g_K[BATCH*NHEADS*SEQ*HDIM];
__device__ float g_V[BATCH*NHEADS*SEQ*HDIM];

// ===================== helpers =====================
__device__ __forceinline__ uint32_t smem_u32(const void* p) {
    uint32_t a;
    asm("{ .reg .u64 t; cvta.to.shared.u64 t, %1; cvt.u32.u64 %0, t; }"
        : "=r"(a) : "l"(p));
    return a;
}
__device__ __forceinline__ void ldsm4(uint32_t* r, uint32_t a) {
    asm volatile("ldmatrix.sync.aligned.m8n8.x4.shared.b16 {%0,%1,%2,%3}, [%4];"
        : "=r"(r[0]), "=r"(r[1]), "=r"(r[2]), "=r"(r[3]) : "r"(a));
}
__device__ __forceinline__ void ldsm4t(uint32_t* r, uint32_t a) {
    asm volatile("ldmatrix.sync.aligned.m8n8.x4.trans.shared.b16 {%0,%1,%2,%3}, [%4];"
        : "=r"(r[0]), "=r"(r[1]), "=r"(r[2]), "=r"(r[3]) : "r"(a));
}
// D += A * B   (m16n8k16, bf16 in, fp32 accumulate)
__device__ __forceinline__ void mma16816(float* d, const uint32_t* a, const uint32_t* b) {
    asm volatile(
        "mma.sync.aligned.m16n8k16.row.col.f32.bf16.bf16.f32 "
        "{%0,%1,%2,%3}, {%4,%5,%6,%7}, {%8,%9}, {%0,%1,%2,%3};"
        : "+f"(d[0]), "+f"(d[1]), "+f"(d[2]), "+f"(d[3])
        : "r"(a[0]), "r"(a[1]), "r"(a[2]), "r"(a[3]), "r"(b[0]), "r"(b[1]));
}
__device__ __forceinline__ uint32_t pack_hi(float x, float y) {
    __nv_bfloat162 h = __floats2bfloat162_rn(x, y);
    return *reinterpret_cast<uint32_t*>(&h);
}
__device__ __forceinline__ uint32_t pack_lo(float x, float y, uint32_t hi) {
    __nv_bfloat162 h = *reinterpret_cast<__nv_bfloat162*>(&hi);
    return pack_hi(x - __bfloat162float(h.x), y - __bfloat162float(h.y));
}

// ===========================================================================
// Kernel 1: QKV projection.  C[t,o] = sum_k hidden[t,k]*W[o,k] + b[o]
// mma.sync bf16 hi/lo split (hh+hl+lh). CTA 128x128, BK=32, 8 warps (64x32).
// ===========================================================================
#define AP 40   // SMEM pitch in bf16 (80B rows: ldmatrix banks 20r%32 distinct)

__global__ __launch_bounds__(256)
void qkv_mma(const float* __restrict__ hidden,
             const float* __restrict__ Wq, const float* __restrict__ bq,
             const float* __restrict__ Wk, const float* __restrict__ bk,
             const float* __restrict__ Wv, const float* __restrict__ bv)
{
    __shared__ __nv_bfloat16 sAh[128*AP], sAl[128*AP];
    __shared__ __nv_bfloat16 sBh[128*AP], sBl[128*AP];

    const int z = blockIdx.z;
    const float* W    = (z == 0) ? Wq : ((z == 1) ? Wk : Wv);
    const float* bias = (z == 0) ? bq : ((z == 1) ? bk : bv);
    float* dst        = (z == 0) ? g_Q : ((z == 1) ? g_K : g_V);

    const int tid  = threadIdx.x;
    const int lane = tid & 31;
    const int wid  = tid >> 5;
    const int wm   = wid >> 2;   // 0..1
    const int wn   = wid & 3;    // 0..3
    const int m0   = blockIdx.y * 128;
    const int n0   = blockIdx.x * 128;

    const uint32_t aAh = smem_u32(sAh), aAl = smem_u32(sAl);
    const uint32_t aBh = smem_u32(sBh), aBl = smem_u32(sBl);

    float acc[4][4][4];
    #pragma unroll
    for (int mt = 0; mt < 4; mt++)
        #pragma unroll
        for (int nt = 0; nt < 4; nt++)
            #pragma unroll
            for (int q = 0; q < 4; q++) acc[mt][nt][q] = 0.0f;

    for (int kt = 0; kt < HID; kt += 32) {
        #pragma unroll
        for (int r = 0; r < 4; r++) {
            int idx = tid + r * 256;            // 0..1023
            int row = idx >> 3;                 // 0..127
            int c   = (idx & 7) * 4;            // 0..28
            float4 a = *(const float4*)&hidden[(size_t)(m0 + row) * HID + kt + c];
            uint32_t h0 = pack_hi(a.x, a.y), h1 = pack_hi(a.z, a.w);
            *(uint2*)&sAh[row * AP + c] = make_uint2(h0, h1);
            *(uint2*)&sAl[row * AP + c] =
                make_uint2(pack_lo(a.x, a.y, h0), pack_lo(a.z, a.w, h1));
            float4 w = *(const float4*)&W[(size_t)(n0 + row) * HID + kt + c];
            uint32_t g0 = pack_hi(w.x, w.y), g1 = pack_hi(w.z, w.w);
            *(uint2*)&sBh[row * AP + c] = make_uint2(g0, g1);
            *(uint2*)&sBl[row * AP + c] =
                make_uint2(pack_lo(w.x, w.y, g0), pack_lo(w.z, w.w, g1));
        }
        __syncthreads();

        #pragma unroll
        for (int ks = 0; ks < 2; ks++) {
            uint32_t ah[4][4], al[4][4], bh[4][2], bl[4][2];
            // A frags: tiles (m0-7,k0)(m8-15,k0)(m0-7,k8)(m8-15,k8)
            const int arow = wm * 64 + (lane & 15);
            const int acol = ks * 16 + ((lane >> 4) << 3);
            #pragma unroll
            for (int mt = 0; mt < 4; mt++) {
                uint32_t off = (uint32_t)(((arow + mt * 16) * AP + acol) * 2);
                ldsm4(ah[mt], aAh + off);
                ldsm4(al[mt], aAl + off);
            }
            // B frags: tiles (n0-7,k0)(n0-7,k8)(n8-15,k0)(n8-15,k8)
            const int brow = wn * 32 + (lane & 7) + ((lane >> 4) << 3);
            const int bcol = ks * 16 + ((lane >> 3) & 1) * 8;
            #pragma unroll
            for (int np = 0; np < 2; np++) {
                uint32_t off = (uint32_t)(((brow + np * 16) * AP + bcol) * 2);
                uint32_t r4[4];
                ldsm4(r4, aBh + off);
                bh[np*2][0] = r4[0]; bh[np*2][1] = r4[1];
                bh[np*2+1][0] = r4[2]; bh[np*2+1][1] = r4[3];
                ldsm4(r4, aBl + off);
                bl[np*2][0] = r4[0]; bl[np*2][1] = r4[1];
                bl[np*2+1][0] = r4[2]; bl[np*2+1][1] = r4[3];
            }
            #pragma unroll
            for (int mt = 0; mt < 4; mt++)
                #pragma unroll
                for (int nt = 0; nt < 4; nt++) {
                    mma16816(acc[mt][nt], ah[mt], bh[nt]);
                    mma16816(acc[mt][nt], ah[mt], bl[nt]);
                    mma16816(acc[mt][nt], al[mt], bh[nt]);
                }
        }
        __syncthreads();
    }

    // epilogue: scatter to [B,NH,S,HD]
    #pragma unroll
    for (int mt = 0; mt < 4; mt++) {
        int r = m0 + wm * 64 + mt * 16 + (lane >> 2);
        int b = r >> 11;
        int s = r & (SEQ - 1);
        #pragma unroll
        for (int nt = 0; nt < 4; nt++) {
            int o = n0 + wn * 32 + nt * 8 + 2 * (lane & 3);
            int h = o >> 6;
            int d = o & (HDIM - 1);
            size_t p = (((size_t)b * NHEADS + h) * SEQ + s) * HDIM + d;
            *(float2*)&dst[p] =
                make_float2(acc[mt][nt][0] + bias[o], acc[mt][nt][1] + bias[o + 1]);
            *(float2*)&dst[p + 8 * HDIM] =
                make_float2(acc[mt][nt][2] + bias[o], acc[mt][nt][3] + bias[o + 1]);
        }
    }
}

// ===========================================================================
// Kernel 2: flash attention via mma.sync bf16 hi/lo split.
// CTA = 128 q-rows of one (b,h); 8 warps, warp owns 16 q-rows (full rows ->
// warp-local softmax). Q frags register-resident; P stays in registers
// (C-frag -> A-frag repack). K: ldmatrix, V: ldmatrix.trans.
// ===========================================================================
#define KP 72   // SMEM pitch bf16 (144B rows: banks 36r%32=4r distinct)

__global__ __launch_bounds__(256)
void attn_mma(float* __restrict__ out)
{
    __shared__ __nv_bfloat16 sKh[64*KP], sKl[64*KP];
    __shared__ __nv_bfloat16 sVh[64*KP], sVl[64*KP];

    const int tid  = threadIdx.x;
    const int lane = tid & 31;
    const int wid  = tid >> 5;
    const int q0   = blockIdx.x * 128;
    const int bh   = blockIdx.y;
    const size_t base = (size_t)bh * SEQ * HDIM;

    const uint32_t aKh = smem_u32(sKh), aKl = smem_u32(sKl);
    const uint32_t aVh = smem_u32(sVh), aVl = smem_u32(sVl);

    // ---- Q fragments, loaded once from gmem (pre-scaled 1/sqrt(64)) ----
    const int qrow = q0 + wid * 16 + (lane >> 2);
    const int qc   = 2 * (lane & 3);
    uint32_t qh[4][4], ql[4][4];
    #pragma unroll
    for (int kt = 0; kt < 4; kt++) {
        int c = kt * 16 + qc;
        float2 f0 = *(const float2*)&g_Q[base + (size_t)qrow * HDIM + c];
        float2 f1 = *(const float2*)&g_Q[base + (size_t)(qrow + 8) * HDIM + c];
        float2 f2 = *(const float2*)&g_Q[base + (size_t)qrow * HDIM + c + 8];
        float2 f3 = *(const float2*)&g_Q[base + (size_t)(qrow + 8) * HDIM + c + 8];
        f0.x *= 0.125f; f0.y *= 0.125f; f1.x *= 0.125f; f1.y *= 0.125f;
        f2.x *= 0.125f; f2.y *= 0.125f; f3.x *= 0.125f; f3.y *= 0.125f;
        qh[kt][0] = pack_hi(f0.x, f0.y); ql[kt][0] = pack_lo(f0.x, f0.y, qh[kt][0]);
        qh[kt][1] = pack_hi(f1.x, f1.y); ql[kt][1] = pack_lo(f1.x, f1.y, qh[kt][1]);
        qh[kt][2] = pack_hi(f2.x, f2.y); ql[kt][2] = pack_lo(f2.x, f2.y, qh[kt][2]);
        qh[kt][3] = pack_hi(f3.x, f3.y); ql[kt][3] = pack_lo(f3.x, f3.y, qh[kt][3]);
    }

    float m[2] = { -INFINITY, -INFINITY };
    float l[2] = { 0.0f, 0.0f };
    float o[8][4];
    #pragma unroll
    for (int nt = 0; nt < 8; nt++)
        #pragma unroll
        for (int q = 0; q < 4; q++) o[nt][q] = 0.0f;

    for (int kt0 = 0; kt0 < SEQ; kt0 += 64) {
        __syncthreads();   // prev iter done reading sK/sV
        #pragma unroll
        for (int r = 0; r < 4; r++) {
            int idx = tid + r * 256;          // 0..1023
            int row = idx >> 4;               // 0..63
            int c   = (idx & 15) * 4;         // 0..60
            float4 k4 = *(const float4*)&g_K[base + (size_t)(kt0 + row) * HDIM + c];
            uint32_t h0 = pack_hi(k4.x, k4.y), h1 = pack_hi(k4.z, k4.w);
            *(uint2*)&sKh[row * KP + c] = make_uint2(h0, h1);
            *(uint2*)&sKl[row * KP + c] =
                make_uint2(pack_lo(k4.x, k4.y, h0), pack_lo(k4.z, k4.w, h1));
            float4 v4 = *(const float4*)&g_V[base + (size_t)(kt0 + row) * HDIM + c];
            uint32_t g0 = pack_hi(v4.x, v4.y), g1 = pack_hi(v4.z, v4.w);
            *(uint2*)&sVh[row * KP + c] = make_uint2(g0, g1);
            *(uint2*)&sVl[row * KP + c] =
                make_uint2(pack_lo(v4.x, v4.y, g0), pack_lo(v4.z, v4.w, g1));
        }
        __syncthreads();

        // ---- scores S = Q K^T ----
        float s[8][4];
        #pragma unroll
        for (int nt = 0; nt < 8; nt++)
            #pragma unroll
            for (int q = 0; q < 4; q++) s[nt][q] = 0.0f;

        #pragma unroll
        for (int ks = 0; ks < 4; ks++) {
            const int krow = (lane & 7) + ((lane >> 4) << 3);
            const int kcol = ks * 16 + ((lane >> 3) & 1) * 8;
            #pragma unroll
            for (int np = 0; np < 4; np++) {
                uint32_t off = (uint32_t)(((krow + np * 16) * KP + kcol) * 2);
                uint32_t rh[4], rl[4];
                ldsm4(rh, aKh + off);
                ldsm4(rl, aKl + off);
                uint32_t b0h[2] = { rh[0], rh[1] }, b1h[2] = { rh[2], rh[3] };
                uint32_t b0l[2] = { rl[0], rl[1] }, b1l[2] = { rl[2], rl[3] };
                mma16816(s[np*2],   qh[ks], b0h);
                mma16816(s[np*2],   qh[ks], b0l);
                mma16816(s[np*2],   ql[ks], b0h);
                mma16816(s[np*2+1], qh[ks], b1h);
                mma16816(s[np*2+1], qh[ks], b1l);
                mma16816(s[np*2+1], ql[ks], b1h);
            }
        }

        // ---- online softmax (rows: regs {0,1}=row lo, {2,3}=row hi) ----
        float sc0, sc1;
        {
            float mt = -INFINITY;
            #pragma unroll
            for (int nt = 0; nt < 8; nt++)
                mt = fmaxf(mt, fmaxf(s[nt][0], s[nt][1]));
            mt = fmaxf(mt, __shfl_xor_sync(0xffffffffu, mt, 1));
            mt = fmaxf(mt, __shfl_xor_sync(0xffffffffu, mt, 2));
            float mn = fmaxf(m[0], mt);
            sc0 = __expf(m[0] - mn);
            m[0] = mn;
            float ps = 0.0f;
            #pragma unroll
            for (int nt = 0; nt < 8; nt++) {
                s[nt][0] = __expf(s[nt][0] - mn);
                s[nt][1] = __expf(s[nt][1] - mn);
                ps += s[nt][0] + s[nt][1];
            }
            ps += __shfl_xor_sync(0xffffffffu, ps, 1);
            ps += __shfl_xor_sync(0xffffffffu, ps, 2);
            l[0] = l[0] * sc0 + ps;
        }
        {
            float mt = -INFINITY;
            #pragma unroll
            for (int nt = 0; nt < 8; nt++)
                mt = fmaxf(mt, fmaxf(s[nt][2], s[nt][3]));
            mt = fmaxf(mt, __shfl_xor_sync(0xffffffffu, mt, 1));
            mt = fmaxf(mt, __shfl_xor_sync(0xffffffffu, mt, 2));
            float mn = fmaxf(m[1], mt);
            sc1 = __expf(m[1] - mn);
            m[1] = mn;
            float ps = 0.0f;
            #pragma unroll
            for (int nt = 0; nt < 8; nt++) {
                s[nt][2] = __expf(s[nt][2] - mn);
                s[nt][3] = __expf(s[nt][3] - mn);
                ps += s[nt][2] + s[nt][3];
            }
            ps += __shfl_xor_sync(0xffffffffu, ps, 1);
            ps += __shfl_xor_sync(0xffffffffu, ps, 2);
            l[1] = l[1] * sc1 + ps;
        }
        #pragma unroll
        for (int nt = 0; nt < 8; nt++) {
            o[nt][0] *= sc0; o[nt][1] *= sc0;
            o[nt][2] *= sc1; o[nt][3] *= sc1;
        }

        // ---- P: C-frag -> A-frag repack (registers only) ----
        uint32_t ph[4][4], pl[4][4];
        #pragma unroll
        for (int kp = 0; kp < 4; kp++) {
            const int t0 = 2 * kp, t1 = 2 * kp + 1;
            ph[kp][0] = pack_hi(s[t0][0], s[t0][1]); pl[kp][0] = pack_lo(s[t0][0], s[t0][1], ph[kp][0]);
            ph[kp][1] = pack_hi(s[t0][2], s[t0][3]); pl[kp][1] = pack_lo(s[t0][2], s[t0][3], ph[kp][1]);
            ph[kp][2] = pack_hi(s[t1][0], s[t1][1]); pl[kp][2] = pack_lo(s[t1][0], s[t1][1], ph[kp][2]);
            ph[kp][3] = pack_hi(s[t1][2], s[t1][3]); pl[kp][3] = pack_lo(s[t1][2], s[t1][3], ph[kp][3]);
        }

        // ---- O += P V ----
        #pragma unroll
        for (int kp = 0; kp < 4; kp++) {
            const int vrow = kp * 16 + (lane & 7) + (((lane >> 3) & 1) << 3);
            #pragma unroll
            for (int np = 0; np < 4; np++) {
                const int vcol = np * 16 + ((lane >> 4) << 3);
                uint32_t off = (uint32_t)((vrow * KP + vcol) * 2);
                uint32_t rh[4], rl[4];
                ldsm4t(rh, aVh + off);
                ldsm4t(rl, aVl + off);
                uint32_t b0h[2] = { rh[0], rh[1] }, b1h[2] = { rh[2], rh[3] };
                uint32_t b0l[2] = { rl[0], rl[1] }, b1l[2] = { rl[2], rl[3] };
                mma16816(o[np*2],   ph[kp], b0h);
                mma16816(o[np*2],   ph[kp], b0l);
                mma16816(o[np*2],   pl[kp], b0h);
                mma16816(o[np*2+1], ph[kp], b1h);
                mma16816(o[np*2+1], ph[kp], b1l);
                mma16816(o[np*2+1], pl[kp], b1h);
            }
        }
    }

    // ---- epilogue ----
    const int b = bh >> 4;
    const int h = bh & (NHEADS - 1);
    const float inv0 = 1.0f / l[0];
    const float inv1 = 1.0f / l[1];
    const int r = q0 + wid * 16 + (lane >> 2);
    #pragma unroll
    for (int nt = 0; nt < 8; nt++) {
        int d = nt * 8 + 2 * (lane & 3);
        *(float2*)&out[((size_t)b * SEQ + r) * HID + h * HDIM + d] =
            make_float2(o[nt][0] * inv0, o[nt][1] * inv0);
        *(float2*)&out[((size_t)b * SEQ + r + 8) * HID + h * HDIM + d] =
            make_float2(o[nt][2] * inv1, o[nt][3] * inv1);
    }
}

// ---------------------------------------------------------------------------
extern "C" void kernel_launch(void* const* d_in, const int* in_sizes, int n_in,
                              void* d_out, int out_size)
{
    const float* hidden = (const float*)d_in[0];
    const float* Wq = (const float*)d_in[1];
    const float* bq = (const float*)d_in[2];
    const float* Wk = (const float*)d_in[3];
    const float* bk = (const float*)d_in[4];
    const float* Wv = (const float*)d_in[5];
    const float* bv = (const float*)d_in[6];
    float* out = (float*)d_out;

    qkv_mma<<<dim3(HID / 128, TOKS / 128, 3), 256>>>(hidden, Wq, bq, Wk, bk, Wv, bv);
    attn_mma<<<dim3(SEQ / 128, BATCH * NHEADS), 256>>>(out);
}